// round 1
// baseline (speedup 1.0000x reference)
#include <cuda_runtime.h>
#include <cstdint>
#include <cstddef>

#define NB   1024
#define CIN  384
#define HWSZ 361
#define P96  96
#define CP   48
#define CG   48

// scratch (device globals: allocation-free per harness rules)
__device__ float g_outp[(size_t)NB * CP * HWSZ];   // ~71 MB
__device__ float g_sum[NB * CG];
__device__ float g_max[NB * CG];
__device__ float g_add[NB * CP];
__device__ float g_pass[NB * 2];

typedef unsigned long long ull;

__device__ __forceinline__ ull pack2(float lo, float hi) {
    ull r; asm("mov.b64 %0, {%1,%2};" : "=l"(r) : "f"(lo), "f"(hi)); return r;
}
__device__ __forceinline__ float2 unpack2(ull v) {
    float2 r; asm("mov.b64 {%0,%1}, %2;" : "=f"(r.x), "=f"(r.y) : "l"(v)); return r;
}
__device__ __forceinline__ ull fma2(ull a, ull b, ull c) {
    ull d; asm("fma.rn.f32x2 %0, %1, %2, %3;" : "=l"(d) : "l"(a), "l"(b), "l"(c)); return d;
}

// ---------------------------------------------------------------------------
// Kernel 1: fused 96x384 channel GEMM + beta/relu/mask + global pool (outg),
// outp channels stored to scratch. One CTA per batch element.
// ---------------------------------------------------------------------------
extern "C" __global__ void __launch_bounds__(384, 1)
k1_gemm_pool(const float* __restrict__ x, const float* __restrict__ mask,
             const float* __restrict__ w1p, const float* __restrict__ w1g,
             const float* __restrict__ betag)
{
    extern __shared__ float smem[];           // [CIN][P96] weights + reduction
    float* Wt  = smem;                        // transposed: Wt[c*96 + p]
    float* rs  = smem + CIN * P96;            // [12][48] warp partial sums
    float* rm  = rs + 12 * 48;                // [12][48] warp partial maxes

    const int n   = blockIdx.x;
    const int tid = threadIdx.x;

    // stage weights transposed into smem (one-time, coalesced global reads)
    for (int i = tid; i < P96 * CIN; i += 384) {
        int p = i / CIN, c = i % CIN;
        float v = (p < 48) ? w1p[i] : w1g[i - 48 * CIN];
        Wt[c * P96 + p] = v;
    }
    __syncthreads();

    ull acc[48];
    #pragma unroll
    for (int j = 0; j < 48; j++) acc[j] = 0ull;

    const int  hw     = tid;
    const bool active = (hw < HWSZ);
    const float* xn = x + (size_t)n * CIN * HWSZ + hw;
    const ulonglong2* ws2 = (const ulonglong2*)Wt;    // 16B-aligned rows (384B/row)

    if (active) {
        // depth-4 register ring prefetch of x[n, c, hw]
        float xbuf[4];
        #pragma unroll
        for (int i = 0; i < 4; i++) xbuf[i] = xn[i * HWSZ];

        #pragma unroll 4
        for (int c = 0; c < CIN; c++) {
            float xv = xbuf[c & 3];
            if (c + 4 < CIN) xbuf[c & 3] = xn[(c + 4) * HWSZ];
            ull x2 = pack2(xv, xv);
            const ulonglong2* row = ws2 + c * 24;
            #pragma unroll
            for (int j = 0; j < 24; j++) {
                ulonglong2 w = row[j];                 // LDS.128 broadcast
                acc[2 * j]     = fma2(x2, w.x, acc[2 * j]);
                acc[2 * j + 1] = fma2(x2, w.y, acc[2 * j + 1]);
            }
        }
    }

    const float m = active ? mask[n * HWSZ + hw] : 0.0f;

    // outp channels 0..47 -> scratch (coalesced across hw per channel)
    if (active) {
        float* op = g_outp + (size_t)n * CP * HWSZ + hw;
        #pragma unroll
        for (int j = 0; j < 24; j++) {
            float2 v = unpack2(acc[j]);
            op[(2 * j) * HWSZ]     = v.x;
            op[(2 * j + 1) * HWSZ] = v.y;
        }
    }

    // pooled reduction for outg channels (p = 48..95)
    const int warp = tid >> 5, lane = tid & 31;
    #pragma unroll 4
    for (int g = 0; g < 48; g++) {
        int j = 24 + (g >> 1);
        float2 v2  = unpack2(acc[j]);
        float raw  = (g & 1) ? v2.y : v2.x;
        float v    = active ? fmaxf((raw + __ldg(&betag[g])) * m, 0.0f) : 0.0f;
        float sv   = v;
        float mv   = active ? (v + m - 1.0f) : -3.0e38f;
        #pragma unroll
        for (int off = 16; off > 0; off >>= 1) {
            sv += __shfl_down_sync(0xffffffffu, sv, off);
            mv  = fmaxf(mv, __shfl_down_sync(0xffffffffu, mv, off));
        }
        if (lane == 0) { rs[warp * 48 + g] = sv; rm[warp * 48 + g] = mv; }
    }
    __syncthreads();
    if (tid < 48) {
        float s = 0.0f, mx = -3.0e38f;
        #pragma unroll
        for (int w = 0; w < 12; w++) {
            s  += rs[w * 48 + tid];
            mx  = fmaxf(mx, rm[w * 48 + tid]);
        }
        g_sum[n * 48 + tid] = s;
        g_max[n * 48 + tid] = mx;
    }
}

// ---------------------------------------------------------------------------
// Kernel 2: pooled features -> pass logits + broadcast add-vector (tiny FCs)
// ---------------------------------------------------------------------------
extern "C" __global__ void __launch_bounds__(64)
k2_pool_fc(const float* __restrict__ msum, const float* __restrict__ wg,
           const float* __restrict__ wpass, const float* __restrict__ bpass,
           const float* __restrict__ w2)
{
    __shared__ float gp[144];
    __shared__ float h[48];
    const int n = blockIdx.x;
    const int t = threadIdx.x;
    const float ms = msum[n];
    if (t < 48) {
        float mean = g_sum[n * 48 + t] / ms;
        gp[t]      = mean;
        gp[48 + t] = mean * (sqrtf(ms) - 14.0f) * 0.1f;
        gp[96 + t] = g_max[n * 48 + t];
    }
    __syncthreads();
    if (t < 48) {
        float d1 = 0.0f, d2 = 0.0f;
        const float* wp  = wpass + t * 144;
        const float* wgr = wg + t * 144;
        #pragma unroll 8
        for (int j = 0; j < 144; j++) {
            float g = gp[j];
            d1 += g * wp[j];
            d2 += g * wgr[j];
        }
        h[t] = fmaxf(d1 + bpass[t], 0.0f);
        g_add[n * 48 + t] = d2;
    }
    __syncthreads();
    if (t == 0) {
        float p0 = 0.0f, p1 = 0.0f;
        #pragma unroll
        for (int i = 0; i < 48; i++) {
            p0 += h[i] * w2[i];
            p1 += h[i] * w2[48 + i];
        }
        g_pass[n * 2 + 0] = p0;
        g_pass[n * 2 + 1] = p1;
    }
}

// ---------------------------------------------------------------------------
// Kernel 3: epilogue — bias/relu/mask, [2,48] conv, assemble [N,6,362] output
// ---------------------------------------------------------------------------
extern "C" __global__ void __launch_bounds__(384)
k3_epilogue(const float* __restrict__ mask, const float* __restrict__ beta2,
            const float* __restrict__ wc2, float* __restrict__ out)
{
    __shared__ float av[48], wc0[48], wc1[48];
    const int n = blockIdx.x;
    const int t = threadIdx.x;
    if (t < 48) {
        av[t]  = g_add[n * 48 + t] + beta2[t];
        wc0[t] = wc2[t];
        wc1[t] = wc2[48 + t];
    }
    __syncthreads();
    float* on = out + (size_t)n * 6 * 362;
    if (t < HWSZ) {
        const float m = mask[n * HWSZ + t];
        const float* ip = g_outp + (size_t)n * CP * HWSZ + t;
        float a0 = 0.0f, a1 = 0.0f;
        #pragma unroll
        for (int p = 0; p < 48; p++) {
            float u = fmaxf((ip[p * HWSZ] + av[p]) * m, 0.0f);
            a0 += u * wc0[p];
            a1 += u * wc1[p];
        }
        float pen = (1.0f - m) * 5000.0f;
        on[t]           = a0 - pen;
        on[5 * 362 + t] = a1 - pen;
        on[1 * 362 + t] = 0.0f;
        on[2 * 362 + t] = 0.0f;
        on[3 * 362 + t] = 0.0f;
        on[4 * 362 + t] = 0.0f;
    } else if (t == HWSZ) {
        on[361]           = g_pass[n * 2 + 0];
        on[5 * 362 + 361] = g_pass[n * 2 + 1];
        on[1 * 362 + 361] = 0.0f;
        on[2 * 362 + 361] = 0.0f;
        on[3 * 362 + 361] = 0.0f;
        on[4 * 362 + 361] = 0.0f;
    }
}

// ---------------------------------------------------------------------------
extern "C" void kernel_launch(void* const* d_in, const int* in_sizes, int n_in,
                              void* d_out, int out_size)
{
    const float* x      = (const float*)d_in[0];
    const float* mask   = (const float*)d_in[1];
    const float* msum   = (const float*)d_in[2];
    const float* w1p    = (const float*)d_in[3];
    const float* w1g    = (const float*)d_in[4];
    const float* betag  = (const float*)d_in[5];
    const float* wling  = (const float*)d_in[6];
    const float* wlinp  = (const float*)d_in[7];
    const float* blinp  = (const float*)d_in[8];
    const float* wlinp2 = (const float*)d_in[9];
    const float* beta2  = (const float*)d_in[10];
    const float* wc2    = (const float*)d_in[11];
    float* out = (float*)d_out;

    const int smem1 = CIN * P96 * 4 + 12 * 48 * 2 * 4;   // 152,064 B
    cudaFuncSetAttribute(k1_gemm_pool,
                         cudaFuncAttributeMaxDynamicSharedMemorySize, smem1);

    k1_gemm_pool<<<NB, 384, smem1>>>(x, mask, w1p, w1g, betag);
    k2_pool_fc<<<NB, 64>>>(msum, wling, wlinp, blinp, wlinp2);
    k3_epilogue<<<NB, 384>>>(mask, beta2, wc2, out);
}

// round 4
// speedup vs baseline: 6.2313x; 6.2313x over previous
#include <cuda_runtime.h>
#include <cstdint>
#include <cstddef>

#define NB   1024
#define CIN  384
#define HWSZ 361
#define P96  96

typedef unsigned long long ull;

__device__ __forceinline__ ull pack2(float lo, float hi) {
    ull r; asm("mov.b64 %0, {%1,%2};" : "=l"(r) : "f"(lo), "f"(hi)); return r;
}
__device__ __forceinline__ float2 unpack2(ull v) {
    float2 r; asm("mov.b64 {%0,%1}, %2;" : "=f"(r.x), "=f"(r.y) : "l"(v)); return r;
}
__device__ __forceinline__ ull fma2(ull a, ull b, ull c) {
    ull d; asm("fma.rn.f32x2 %0, %1, %2, %3;" : "=l"(d) : "l"(a), "l"(b), "l"(c)); return d;
}

// ---------------------------------------------------------------------------
// Single fused kernel. One CTA (768 threads) per batch element n.
//   threads   0..383 : hw = tid,      computes p-channels 0..47 (outp half)
//   threads 384..767 : hw = tid-384,  computes g-channels 0..47 (outg half)
// GEMM -> pool (g-half) -> tiny FCs -> epilogue (p-half regs) -> output.
// ---------------------------------------------------------------------------
extern "C" __global__ void __launch_bounds__(768, 1)
k_fused(const float* __restrict__ x, const float* __restrict__ mask,
        const float* __restrict__ msum,
        const float* __restrict__ w1p, const float* __restrict__ w1g,
        const float* __restrict__ betag,
        const float* __restrict__ wling, const float* __restrict__ wlinp,
        const float* __restrict__ blinp, const float* __restrict__ wlinp2,
        const float* __restrict__ beta2, const float* __restrict__ wc2,
        float* __restrict__ out)
{
    extern __shared__ float smem[];
    float* Wt = smem;                      // [CIN][96] transposed weights
    float* rs = smem + CIN * P96;          // [12][48] warp partial sums
    float* rm = rs + 12 * 48;              // [12][48] warp partial maxes
    float* gp = rm + 12 * 48;              // [144] pooled features
    float* hv = gp + 144;                  // [48] pass hidden
    float* av = hv + 48;                   // [48] g_add + beta2
    float* wcs = av + 48;                  // [96] conv2 weights
    float* pv = wcs + 96;                  // [2] pass logits

    const int n   = blockIdx.x;
    const int tid = threadIdx.x;
    const bool is_g = (tid >= 384);
    const int hw    = is_g ? tid - 384 : tid;
    const bool active = (hw < HWSZ);

    // stage weights transposed into smem (incremental p/c indexing)
    {
        int p = tid / CIN, c = tid % CIN;          // 768 = 2*CIN -> p in {0,1}
        for (int i = tid; i < P96 * CIN; i += 768) {
            float v = (p < 48) ? w1p[p * CIN + c] : w1g[(p - 48) * CIN + c];
            Wt[c * P96 + p] = v;
            p += 2;                                 // stride 768 = 2 rows of CIN
        }
    }
    if (tid < 96) wcs[tid] = wc2[tid];
    __syncthreads();

    ull acc[24];                          // 48 fp32 channels for this half
    #pragma unroll
    for (int j = 0; j < 24; j++) acc[j] = 0ull;

    const float* xn = x + (size_t)n * CIN * HWSZ + hw;
    // full row = 24 ulonglong2 (96 floats); each half reads a 12-wide slice
    const ulonglong2* wbase = (const ulonglong2*)(Wt) + (is_g ? 12 : 0);

    if (active) {
        float xbuf[4];
        #pragma unroll
        for (int i = 0; i < 4; i++) xbuf[i] = xn[i * HWSZ];

        #pragma unroll 2
        for (int c = 0; c < CIN; c++) {
            float xv = xbuf[c & 3];
            if (c + 4 < CIN) xbuf[c & 3] = xn[(c + 4) * HWSZ];
            ull x2 = pack2(xv, xv);
            const ulonglong2* row = wbase + c * 24;      // row stride = 24
            #pragma unroll
            for (int j = 0; j < 12; j++) {
                ulonglong2 w = row[j];                   // LDS.128 broadcast
                acc[2 * j]     = fma2(x2, w.x, acc[2 * j]);
                acc[2 * j + 1] = fma2(x2, w.y, acc[2 * j + 1]);
            }
        }
    }

    const float m = active ? mask[n * HWSZ + hw] : 0.0f;

    // ---- g-half: bias + relu + mask, then pooled reduction ----
    if (is_g) {
        const int warp = (tid >> 5) - 12;    // 0..11
        const int lane = tid & 31;
        #pragma unroll 4
        for (int g = 0; g < 48; g++) {
            float2 v2 = unpack2(acc[g >> 1]);
            float raw = (g & 1) ? v2.y : v2.x;
            float v   = active ? fmaxf((raw + __ldg(&betag[g])) * m, 0.0f) : 0.0f;
            float sv  = v;
            float mv  = active ? (v + m - 1.0f) : -3.0e38f;
            #pragma unroll
            for (int off = 16; off > 0; off >>= 1) {
                sv += __shfl_down_sync(0xffffffffu, sv, off);
                mv  = fmaxf(mv, __shfl_down_sync(0xffffffffu, mv, off));
            }
            if (lane == 0) { rs[warp * 48 + g] = sv; rm[warp * 48 + g] = mv; }
        }
    }
    __syncthreads();

    // ---- pooled features ----
    const float ms = msum[n];
    if (tid < 48) {
        float s = 0.0f, mx = -3.0e38f;
        #pragma unroll
        for (int w = 0; w < 12; w++) {
            s  += rs[w * 48 + tid];
            mx  = fmaxf(mx, rm[w * 48 + tid]);
        }
        float mean = s / ms;
        gp[tid]      = mean;
        gp[48 + tid] = mean * (sqrtf(ms) - 14.0f) * 0.1f;
        gp[96 + tid] = mx;
    }
    __syncthreads();

    // ---- tiny FCs: pass hidden + broadcast add-vector ----
    if (tid < 48) {
        float d1 = 0.0f, d2 = 0.0f;
        const float* wp  = wlinp + tid * 144;
        const float* wgr = wling + tid * 144;
        #pragma unroll 8
        for (int j = 0; j < 144; j++) {
            float g = gp[j];
            d1 += g * wp[j];
            d2 += g * wgr[j];
        }
        hv[tid] = fmaxf(d1 + blinp[tid], 0.0f);
        av[tid] = d2 + beta2[tid];
    }
    __syncthreads();
    if (tid < 2) {
        float p = 0.0f;
        const float* w2 = wlinp2 + tid * 48;
        #pragma unroll
        for (int i = 0; i < 48; i++) p += hv[i] * w2[i];
        pv[tid] = p;
    }
    __syncthreads();

    // ---- epilogue: p-half registers -> relu -> [2,48] conv -> output ----
    float* on = out + (size_t)n * 6 * 362;
    if (!is_g) {
        if (active) {
            float a0 = 0.0f, a1 = 0.0f;
            #pragma unroll
            for (int j = 0; j < 24; j++) {
                float2 v = unpack2(acc[j]);
                int p0 = 2 * j, p1 = 2 * j + 1;
                float u0 = fmaxf((v.x + av[p0]) * m, 0.0f);
                float u1 = fmaxf((v.y + av[p1]) * m, 0.0f);
                a0 += u0 * wcs[p0]      + u1 * wcs[p1];
                a1 += u0 * wcs[48 + p0] + u1 * wcs[48 + p1];
            }
            float pen = (1.0f - m) * 5000.0f;
            on[hw]           = a0 - pen;
            on[5 * 362 + hw] = a1 - pen;
        } else if (hw == HWSZ) {
            on[361]           = pv[0];
            on[5 * 362 + 361] = pv[1];
        }
    }
    // zero channels 1..4 (4*362 = 1448 floats) with all threads
    for (int i = tid; i < 4 * 362; i += 768) on[362 + i] = 0.0f;
}

// ---------------------------------------------------------------------------
extern "C" void kernel_launch(void* const* d_in, const int* in_sizes, int n_in,
                              void* d_out, int out_size)
{
    const float* x      = (const float*)d_in[0];
    const float* mask   = (const float*)d_in[1];
    const float* msum   = (const float*)d_in[2];
    const float* w1p    = (const float*)d_in[3];
    const float* w1g    = (const float*)d_in[4];
    const float* betag  = (const float*)d_in[5];
    const float* wling  = (const float*)d_in[6];
    const float* wlinp  = (const float*)d_in[7];
    const float* blinp  = (const float*)d_in[8];
    const float* wlinp2 = (const float*)d_in[9];
    const float* beta2  = (const float*)d_in[10];
    const float* wc2    = (const float*)d_in[11];
    float* out = (float*)d_out;

    const int smem = (CIN * P96 + 12 * 48 * 2 + 144 + 48 + 48 + 96 + 2 + 2) * 4;
    cudaFuncSetAttribute(k_fused,
                         cudaFuncAttributeMaxDynamicSharedMemorySize, smem);

    k_fused<<<NB, 768, smem>>>(x, mask, msum, w1p, w1g, betag,
                               wling, wlinp, blinp, wlinp2, beta2, wc2, out);
}

// round 5
// speedup vs baseline: 8.2091x; 1.3174x over previous
#include <cuda_runtime.h>
#include <cstdint>
#include <cstddef>

#define NB   1024
#define CIN  384
#define HWSZ 361
#define P96  96

typedef unsigned long long ull;

__device__ __forceinline__ ull pack2(float lo, float hi) {
    ull r; asm("mov.b64 %0, {%1,%2};" : "=l"(r) : "f"(lo), "f"(hi)); return r;
}
__device__ __forceinline__ float2 unpack2(ull v) {
    float2 r; asm("mov.b64 {%0,%1}, %2;" : "=f"(r.x), "=f"(r.y) : "l"(v)); return r;
}
__device__ __forceinline__ ull fma2(ull a, ull b, ull c) {
    ull d; asm("fma.rn.f32x2 %0, %1, %2, %3;" : "=l"(d) : "l"(a), "l"(b), "l"(c)); return d;
}

// ---------------------------------------------------------------------------
// One CTA (768 threads) per batch n. Quarter layout:
//   q = tid/192 : q0 -> p-ch  0..23, q1 -> p-ch 24..47,
//                 q2 -> g-ch  0..23, q3 -> g-ch 24..47   (absolute 48..95)
//   s = tid%192 : hw0 = s (always active), hw1 = s+192 (active if s<169)
// Each thread: 24 channels x 2 hw -> 24 ull accumulators (48 regs).
// ---------------------------------------------------------------------------
extern "C" __global__ void __launch_bounds__(768, 1)
k_fused(const float* __restrict__ x, const float* __restrict__ mask,
        const float* __restrict__ msum,
        const float* __restrict__ w1p, const float* __restrict__ w1g,
        const float* __restrict__ betag,
        const float* __restrict__ wling, const float* __restrict__ wlinp,
        const float* __restrict__ blinp, const float* __restrict__ wlinp2,
        const float* __restrict__ beta2, const float* __restrict__ wc2,
        float* __restrict__ out)
{
    extern __shared__ float smem[];
    float* Wt  = smem;                     // [CIN][96]
    float* rs  = smem + CIN * P96;         // [12][24] warp partial sums (g)
    float* rm  = rs + 12 * 24;             // [12][24] warp partial maxes (g)
    float* gp  = rm + 12 * 24;             // [144] pooled features
    float* hv  = gp + 144;                 // [48] pass hidden
    float* av  = hv + 48;                  // [48] g_add + beta2
    float* wcs = av + 48;                  // [96] conv2 weights
    float* pv  = wcs + 96;                 // [2] pass logits
    float* pa0 = pv + 2;                   // [384] partial a0 per hw
    float* pa1 = pa0 + 384;                // [384] partial a1 per hw

    const int n   = blockIdx.x;
    const int tid = threadIdx.x;
    const int q   = tid / 192;             // 0..3
    const int s   = tid % 192;
    const bool act1 = (s < 169);           // hw1 = s+192 <= 360
    const int hw1 = act1 ? (s + 192) : 360;

    // stage weights transposed into smem
    {
        int p = tid / CIN, c = tid % CIN;
        for (int i = tid; i < P96 * CIN; i += 768) {
            float v = (p < 48) ? w1p[p * CIN + c] : w1g[(p - 48) * CIN + c];
            Wt[c * P96 + p] = v;
            p += 2;
        }
    }
    if (tid < 96) wcs[tid] = wc2[tid];
    __syncthreads();

    ull acc0[12], acc1[12];
    #pragma unroll
    for (int j = 0; j < 12; j++) { acc0[j] = 0ull; acc1[j] = 0ull; }

    const float* xn = x + (size_t)n * CIN * HWSZ;
    const float* p0 = xn + s;
    const float* p1 = xn + hw1;
    const ulonglong2* wbase = (const ulonglong2*)Wt + q * 6;  // 24-ch slice

    {
        float xb0[4], xb1[4];
        #pragma unroll
        for (int i = 0; i < 4; i++) { xb0[i] = p0[i * HWSZ]; xb1[i] = p1[i * HWSZ]; }

        #pragma unroll 4
        for (int c = 0; c < CIN; c++) {
            float xv0 = xb0[c & 3];
            float xv1 = xb1[c & 3];
            if (c + 4 < CIN) {
                xb0[c & 3] = p0[(c + 4) * HWSZ];
                xb1[c & 3] = p1[(c + 4) * HWSZ];
            }
            ull x20 = pack2(xv0, xv0);
            ull x21 = pack2(xv1, xv1);
            const ulonglong2* row = wbase + c * 24;     // full row = 24 ull2
            #pragma unroll
            for (int j = 0; j < 6; j++) {
                ulonglong2 w = row[j];                  // LDS.128, 4 weights
                acc0[2 * j]     = fma2(x20, w.x, acc0[2 * j]);
                acc0[2 * j + 1] = fma2(x20, w.y, acc0[2 * j + 1]);
                acc1[2 * j]     = fma2(x21, w.x, acc1[2 * j]);
                acc1[2 * j + 1] = fma2(x21, w.y, acc1[2 * j + 1]);
            }
        }
    }

    const float m0 = mask[n * HWSZ + s];
    const float m1 = act1 ? mask[n * HWSZ + s + 192] : 0.0f;

    // ---- g-quarters: bias+relu+mask, pooled reduction over 2 hw ----
    if (q >= 2) {
        const int gwarp = (tid >> 5) - 12;     // 0..11
        const int lane  = tid & 31;
        const int gbase = (q - 2) * 24;        // 0 or 24 (g-channel offset)
        #pragma unroll 4
        for (int gl = 0; gl < 24; gl++) {
            float2 v0 = unpack2(acc0[gl >> 1]);
            float2 v1 = unpack2(acc1[gl >> 1]);
            float r0 = (gl & 1) ? v0.y : v0.x;
            float r1 = (gl & 1) ? v1.y : v1.x;
            float b  = __ldg(&betag[gbase + gl]);
            float u0 = fmaxf((r0 + b) * m0, 0.0f);
            float u1 = act1 ? fmaxf((r1 + b) * m1, 0.0f) : 0.0f;
            float sv = u0 + u1;
            float mv = fmaxf(u0 + m0 - 1.0f, act1 ? (u1 + m1 - 1.0f) : -3.0e38f);
            #pragma unroll
            for (int off = 16; off > 0; off >>= 1) {
                sv += __shfl_down_sync(0xffffffffu, sv, off);
                mv  = fmaxf(mv, __shfl_down_sync(0xffffffffu, mv, off));
            }
            if (lane == 0) { rs[gwarp * 24 + gl] = sv; rm[gwarp * 24 + gl] = mv; }
        }
    }
    __syncthreads();

    // ---- pooled features (48 g-channels) ----
    const float ms = msum[n];
    if (tid < 48) {
        const int wb = (tid < 24) ? 0 : 6;     // q2 warps 0..5, q3 warps 6..11
        const int gl = (tid < 24) ? tid : tid - 24;
        float sum = 0.0f, mx = -3.0e38f;
        #pragma unroll
        for (int w = 0; w < 6; w++) {
            sum += rs[(wb + w) * 24 + gl];
            mx   = fmaxf(mx, rm[(wb + w) * 24 + gl]);
        }
        float mean = sum / ms;
        gp[tid]      = mean;
        gp[48 + tid] = mean * (sqrtf(ms) - 14.0f) * 0.1f;
        gp[96 + tid] = mx;
    }
    __syncthreads();

    // ---- tiny FCs ----
    if (tid < 48) {
        float d1 = 0.0f, d2 = 0.0f;
        const float* wp  = wlinp + tid * 144;
        const float* wgr = wling + tid * 144;
        #pragma unroll 8
        for (int j = 0; j < 144; j++) {
            float g = gp[j];
            d1 += g * wp[j];
            d2 += g * wgr[j];
        }
        hv[tid] = fmaxf(d1 + blinp[tid], 0.0f);
        av[tid] = d2 + beta2[tid];
    }
    __syncthreads();
    if (tid < 2) {
        float p = 0.0f;
        const float* w2 = wlinp2 + tid * 48;
        #pragma unroll
        for (int i = 0; i < 48; i++) p += hv[i] * w2[i];
        pv[tid] = p;
    }
    __syncthreads();

    // ---- p epilogue stage 1: q0 partials (ch 0..23) ----
    if (q == 0) {
        float a0h0 = 0.0f, a1h0 = 0.0f, a0h1 = 0.0f, a1h1 = 0.0f;
        #pragma unroll
        for (int j = 0; j < 12; j++) {
            float2 v0 = unpack2(acc0[j]);
            float2 v1 = unpack2(acc1[j]);
            int c0 = 2 * j, c1 = 2 * j + 1;
            float u;
            u = fmaxf((v0.x + av[c0]) * m0, 0.0f); a0h0 += u * wcs[c0]; a1h0 += u * wcs[48 + c0];
            u = fmaxf((v0.y + av[c1]) * m0, 0.0f); a0h0 += u * wcs[c1]; a1h0 += u * wcs[48 + c1];
            u = fmaxf((v1.x + av[c0]) * m1, 0.0f); a0h1 += u * wcs[c0]; a1h1 += u * wcs[48 + c0];
            u = fmaxf((v1.y + av[c1]) * m1, 0.0f); a0h1 += u * wcs[c1]; a1h1 += u * wcs[48 + c1];
        }
        pa0[s] = a0h0;  pa1[s] = a1h0;
        if (act1) { pa0[s + 192] = a0h1; pa1[s + 192] = a1h1; }
    }
    __syncthreads();

    // ---- p epilogue stage 2: q1 adds ch 24..47, writes output ----
    float* on = out + (size_t)n * 6 * 362;
    if (q == 1) {
        float a0h0 = pa0[s], a1h0 = pa1[s];
        float a0h1 = act1 ? pa0[s + 192] : 0.0f;
        float a1h1 = act1 ? pa1[s + 192] : 0.0f;
        #pragma unroll
        for (int j = 0; j < 12; j++) {
            float2 v0 = unpack2(acc0[j]);
            float2 v1 = unpack2(acc1[j]);
            int c0 = 24 + 2 * j, c1 = 24 + 2 * j + 1;
            float u;
            u = fmaxf((v0.x + av[c0]) * m0, 0.0f); a0h0 += u * wcs[c0]; a1h0 += u * wcs[48 + c0];
            u = fmaxf((v0.y + av[c1]) * m0, 0.0f); a0h0 += u * wcs[c1]; a1h0 += u * wcs[48 + c1];
            u = fmaxf((v1.x + av[c0]) * m1, 0.0f); a0h1 += u * wcs[c0]; a1h1 += u * wcs[48 + c0];
            u = fmaxf((v1.y + av[c1]) * m1, 0.0f); a0h1 += u * wcs[c1]; a1h1 += u * wcs[48 + c1];
        }
        float pen0 = (1.0f - m0) * 5000.0f;
        on[s]           = a0h0 - pen0;
        on[5 * 362 + s] = a1h0 - pen0;
        if (act1) {
            float pen1 = (1.0f - m1) * 5000.0f;
            on[s + 192]           = a0h1 - pen1;
            on[5 * 362 + s + 192] = a1h1 - pen1;
        }
    }
    if (tid == 0) {
        on[361]           = pv[0];
        on[5 * 362 + 361] = pv[1];
    }
    // zero channels 1..4
    for (int i = tid; i < 4 * 362; i += 768) on[362 + i] = 0.0f;
}

// ---------------------------------------------------------------------------
extern "C" void kernel_launch(void* const* d_in, const int* in_sizes, int n_in,
                              void* d_out, int out_size)
{
    const float* x      = (const float*)d_in[0];
    const float* mask   = (const float*)d_in[1];
    const float* msum   = (const float*)d_in[2];
    const float* w1p    = (const float*)d_in[3];
    const float* w1g    = (const float*)d_in[4];
    const float* betag  = (const float*)d_in[5];
    const float* wling  = (const float*)d_in[6];
    const float* wlinp  = (const float*)d_in[7];
    const float* blinp  = (const float*)d_in[8];
    const float* wlinp2 = (const float*)d_in[9];
    const float* beta2  = (const float*)d_in[10];
    const float* wc2    = (const float*)d_in[11];
    float* out = (float*)d_out;

    const int smem = (CIN * P96 + 12 * 24 * 2 + 144 + 48 + 48 + 96 + 2
                      + 384 * 2 + 2) * 4;
    cudaFuncSetAttribute(k_fused,
                         cudaFuncAttributeMaxDynamicSharedMemorySize, smem);

    k_fused<<<NB, 768, smem>>>(x, mask, msum, w1p, w1g, betag,
                               wling, wlinp, blinp, wlinp2, beta2, wc2, out);
}